// round 1
// baseline (speedup 1.0000x reference)
#include <cuda_runtime.h>

// Problem constants
#define T_STEPS 301
#define IN_DIM  40
#define H_DIM   64
#define G_DIM   256      // 4*H
#define KTOT    104      // IN + H
#define BTILE   32       // samples per CTA
#define NTHR    256
#define XH_STRIDE 36     // floats per k-row of x/h operand tile (32 samples + pad, 16B-aligned rows)

// Shared memory layout (in floats)
#define WZ_OFF   0
#define WZ_SIZE  (KTOT * G_DIM)          // 26624 : W[k][g], k<40 -> w_ih, else w_hh
#define XH_OFF   (WZ_OFF + WZ_SIZE)
#define XH_SIZE  (KTOT * XH_STRIDE)      // 3744  : operand rows [k][b]
#define BIAS_OFF (XH_OFF + XH_SIZE)      // 256   : b_ih + b_hh
#define CLF_OFF  (BIAS_OFF + G_DIM)
#define CLF_SIZE (BTILE * 65)            // 2080  : classifier partials, padded rows
#define SMEM_FLOATS (CLF_OFF + CLF_SIZE) // 32704 floats = 130816 bytes

typedef unsigned long long ull;

__device__ __forceinline__ ull pack2(float a, float b) {
    ull r; asm("mov.b64 %0, {%1,%2};" : "=l"(r) : "f"(a), "f"(b)); return r;
}
__device__ __forceinline__ void unpack2(ull v, float& a, float& b) {
    asm("mov.b64 {%0,%1}, %2;" : "=f"(a), "=f"(b) : "l"(v));
}
// packed fp32x2 FMA (sm_100+): d = a*b + d
__device__ __forceinline__ void ffma2(ull& d, ull a, ull b) {
    asm("fma.rn.f32x2 %0, %1, %2, %0;" : "+l"(d) : "l"(a), "l"(b));
}
__device__ __forceinline__ float sigm(float x) {
    return __fdividef(1.f, 1.f + __expf(-x));
}
__device__ __forceinline__ float tanhx(float x) {
    // 1 - 2/(e^{2x}+1); saturates correctly at +/-inf
    float e = __expf(2.f * x);
    return 1.f - __fdividef(2.f, e + 1.f);
}

__global__ void __launch_bounds__(NTHR, 1)
lstm_fused_kernel(const float* __restrict__ x,
                  const float* __restrict__ w_ih,
                  const float* __restrict__ w_hh,
                  const float* __restrict__ b_ih,
                  const float* __restrict__ b_hh,
                  const float* __restrict__ w_clf,
                  const float* __restrict__ b_clf,
                  float* __restrict__ out)
{
    extern __shared__ float sm[];
    float* Wz    = sm + WZ_OFF;    // [KTOT][256]
    float* xhf   = sm + XH_OFF;    // [KTOT][XH_STRIDE], float index b in [0,32)
    float* bias  = sm + BIAS_OFF;  // [256]
    float* shclf = sm + CLF_OFF;   // [32][65]

    const int tid  = threadIdx.x;
    const int j    = tid & 63;     // gate column within H
    const int bt   = tid >> 6;     // which group of 8 samples (0..3)
    const int base = blockIdx.x * BTILE;

    // ---- stage weights transposed into [k][g] ----
    for (int idx = tid; idx < WZ_SIZE; idx += NTHR) {
        int g = idx & 255, k = idx >> 8;
        Wz[idx] = (k < IN_DIM) ? w_ih[g * IN_DIM + k]
                               : w_hh[g * H_DIM + (k - IN_DIM)];
    }
    bias[tid] = b_ih[tid] + b_hh[tid];
    // zero h rows (t=0 hidden state)
    for (int f = tid; f < H_DIM * BTILE; f += NTHR)
        xhf[(IN_DIM + (f >> 5)) * XH_STRIDE + (f & 31)] = 0.f;

    // ---- initial x prefetch (t = 0): 1280 floats / 256 thr = 5 each ----
    float xr[5];
    #pragma unroll
    for (int i = 0; i < 5; i++) {
        int f = tid + i * NTHR;
        int b = f / IN_DIM, k = f - b * IN_DIM;
        xr[i] = x[(size_t)(base + b) * (T_STEPS * IN_DIM) + k];
    }

    float c[8], clf[8];
    #pragma unroll
    for (int i = 0; i < 8; i++) { c[i] = 0.f; clf[i] = 0.f; }

    ull acc[4][4];   // [gate][sample-pair], f32x2 lanes = (b_even, b_odd)

    for (int t = 0; t < T_STEPS; t++) {
        // store prefetched x_t into operand tile (x region only; disjoint from h rows)
        #pragma unroll
        for (int i = 0; i < 5; i++) {
            int f = tid + i * NTHR;
            int b = f / IN_DIM, k = f - b * IN_DIM;
            xhf[k * XH_STRIDE + b] = xr[i];
        }
        // prefetch x_{t+1} (overlaps with this step's GEMM)
        if (t + 1 < T_STEPS) {
            #pragma unroll
            for (int i = 0; i < 5; i++) {
                int f = tid + i * NTHR;
                int b = f / IN_DIM, k = f - b * IN_DIM;
                xr[i] = x[(size_t)(base + b) * (T_STEPS * IN_DIM) + (t + 1) * IN_DIM + k];
            }
        }
        float wc = __ldg(&w_clf[t * H_DIM + j]);   // classifier weight for this step/column

        __syncthreads();   // x_t staged + h_{t-1} staged before GEMM reads

        // init accumulators with bias
        #pragma unroll
        for (int g = 0; g < 4; g++) {
            float bg = bias[j + 64 * g];
            ull bp = pack2(bg, bg);
            #pragma unroll
            for (int p = 0; p < 4; p++) acc[g][p] = bp;
        }

        // ---- z = [x_t ; h_{t-1}] @ W^T : 104-deep, 16 f32x2 accs/thread ----
        const float* xrow = xhf + 8 * bt;
        #pragma unroll 8
        for (int k = 0; k < KTOT; k++) {
            const float* wr = Wz + k * G_DIM + j;
            float w0 = wr[0], w1 = wr[64], w2 = wr[128], w3 = wr[192];
            ull W0 = pack2(w0, w0), W1 = pack2(w1, w1);
            ull W2 = pack2(w2, w2), W3 = pack2(w3, w3);
            ulonglong2 xlo = *(const ulonglong2*)(xrow + k * XH_STRIDE);      // samples 8bt..8bt+3
            ulonglong2 xhi = *(const ulonglong2*)(xrow + k * XH_STRIDE + 4);  // samples 8bt+4..8bt+7
            ffma2(acc[0][0], W0, xlo.x); ffma2(acc[0][1], W0, xlo.y);
            ffma2(acc[0][2], W0, xhi.x); ffma2(acc[0][3], W0, xhi.y);
            ffma2(acc[1][0], W1, xlo.x); ffma2(acc[1][1], W1, xlo.y);
            ffma2(acc[1][2], W1, xhi.x); ffma2(acc[1][3], W1, xhi.y);
            ffma2(acc[2][0], W2, xlo.x); ffma2(acc[2][1], W2, xlo.y);
            ffma2(acc[2][2], W2, xhi.x); ffma2(acc[2][3], W2, xhi.y);
            ffma2(acc[3][0], W3, xlo.x); ffma2(acc[3][1], W3, xlo.y);
            ffma2(acc[3][2], W3, xhi.x); ffma2(acc[3][3], W3, xhi.y);
        }

        __syncthreads();   // all GEMM reads of xhf done before h rows are overwritten

        // ---- gates: i,f,g,o all in this thread's registers ----
        #pragma unroll
        for (int p = 0; p < 4; p++) {
            float zi0, zi1, zf0, zf1, zg0, zg1, zo0, zo1;
            unpack2(acc[0][p], zi0, zi1);
            unpack2(acc[1][p], zf0, zf1);
            unpack2(acc[2][p], zg0, zg1);
            unpack2(acc[3][p], zo0, zo1);

            float cc0 = c[2 * p];
            cc0 = sigm(zf0) * cc0 + sigm(zi0) * tanhx(zg0);
            float h0 = sigm(zo0) * tanhx(cc0);
            c[2 * p] = cc0;
            clf[2 * p] += h0 * wc;
            xhf[(IN_DIM + j) * XH_STRIDE + 8 * bt + 2 * p] = h0;

            float cc1 = c[2 * p + 1];
            cc1 = sigm(zf1) * cc1 + sigm(zi1) * tanhx(zg1);
            float h1 = sigm(zo1) * tanhx(cc1);
            c[2 * p + 1] = cc1;
            clf[2 * p + 1] += h1 * wc;
            xhf[(IN_DIM + j) * XH_STRIDE + 8 * bt + 2 * p + 1] = h1;
        }
    }

    // ---- classifier reduction over j ----
    #pragma unroll
    for (int p = 0; p < 4; p++) {
        shclf[(8 * bt + 2 * p)     * 65 + j] = clf[2 * p];
        shclf[(8 * bt + 2 * p + 1) * 65 + j] = clf[2 * p + 1];
    }
    __syncthreads();
    if (tid < BTILE) {
        float s = b_clf[0];
        #pragma unroll 8
        for (int jj = 0; jj < H_DIM; jj++) s += shclf[tid * 65 + jj];
        out[base + tid] = s;
    }
}

extern "C" void kernel_launch(void* const* d_in, const int* in_sizes, int n_in,
                              void* d_out, int out_size)
{
    const float* x     = (const float*)d_in[0];
    const float* w_ih  = (const float*)d_in[1];
    const float* w_hh  = (const float*)d_in[2];
    const float* b_ih  = (const float*)d_in[3];
    const float* b_hh  = (const float*)d_in[4];
    const float* w_clf = (const float*)d_in[5];
    const float* b_clf = (const float*)d_in[6];
    float* out = (float*)d_out;

    const int B = in_sizes[0] / (T_STEPS * IN_DIM);   // 4096
    const int smem_bytes = SMEM_FLOATS * sizeof(float);

    cudaFuncSetAttribute(lstm_fused_kernel,
                         cudaFuncAttributeMaxDynamicSharedMemorySize, smem_bytes);
    lstm_fused_kernel<<<B / BTILE, NTHR, smem_bytes>>>(
        x, w_ih, w_hh, b_ih, b_hh, w_clf, b_clf, out);
}